// round 2
// baseline (speedup 1.0000x reference)
#include <cuda_runtime.h>
#include <cuda_bf16.h>
#include <math.h>

#define N_NODES 1000000
#define N_EDGES 16000000
#define F1 16

// ---- scratch (device globals; no allocation allowed) ----
__device__ float  g_deg[N_NODES];
__device__ float  g_dis[N_NODES];          // rsqrt(deg + 1)
__device__ float4 g_h[N_NODES * 4];        // [N,16] projected features
__device__ float4 g_agg[N_NODES * 4];      // [N,16] layer-1 aggregation
__device__ float  g_h2[N_NODES];           // [N] layer-2 projected feature

// ---------------- kernels ----------------

__global__ void k_zero_deg() {
    int i = blockIdx.x * blockDim.x + threadIdx.x;
    if (i < N_NODES) g_deg[i] = 0.0f;
}

// per edge: accumulate weighted degree at dst
__global__ void k_deg(const int* __restrict__ dst,
                      const float* __restrict__ ew) {
    int e = blockIdx.x * blockDim.x + threadIdx.x;
    if (e >= N_EDGES) return;
    int d = dst[e];
    if ((unsigned)d >= N_NODES) return;   // guard: wrong-dtype safety
    atomicAdd(&g_deg[d], ew[e]);
}

__global__ void k_dis() {
    int i = blockIdx.x * blockDim.x + threadIdx.x;
    if (i < N_NODES) {
        float deg = g_deg[i] + 1.0f;   // + self-loop weight
        g_dis[i] = rsqrtf(deg);        // deg >= 1 always > 0
    }
}

// h = x @ W1; also seed agg with the self-loop contribution dis^2 * h
__global__ void k_proj1(const float* __restrict__ x,
                        const float* __restrict__ W1) {
    __shared__ float sW1[25 * F1];
    for (int t = threadIdx.x; t < 25 * F1; t += blockDim.x) sW1[t] = W1[t];
    __syncthreads();

    int i = blockIdx.x * blockDim.x + threadIdx.x;
    if (i >= N_NODES) return;

    const float* xr = x + (size_t)i * 25;
    float a[F1];
#pragma unroll
    for (int f = 0; f < F1; f++) a[f] = 0.0f;
#pragma unroll
    for (int k = 0; k < 25; k++) {
        float xv = __ldg(xr + k);
#pragma unroll
        for (int f = 0; f < F1; f++) a[f] = fmaf(xv, sW1[k * F1 + f], a[f]);
    }

    float s = g_dis[i];
    float s2 = s * s;
#pragma unroll
    for (int q = 0; q < 4; q++) {
        float4 hv = make_float4(a[4*q+0], a[4*q+1], a[4*q+2], a[4*q+3]);
        g_h[i * 4 + q] = hv;
        g_agg[i * 4 + q] = make_float4(s2*hv.x, s2*hv.y, s2*hv.z, s2*hv.w);
    }
}

__device__ __forceinline__ void red_v4(float4* addr, float4 v) {
    asm volatile("red.global.add.v4.f32 [%0], {%1,%2,%3,%4};"
                 :: "l"(addr), "f"(v.x), "f"(v.y), "f"(v.z), "f"(v.w)
                 : "memory");
}

// layer-1 edge scatter: agg[dst] += norm * h[src]
__global__ void k_agg1(const int* __restrict__ src,
                       const int* __restrict__ dst,
                       const float* __restrict__ ew) {
    int e = blockIdx.x * blockDim.x + threadIdx.x;
    if (e >= N_EDGES) return;
    int s = src[e], d = dst[e];
    if ((unsigned)s >= N_NODES || (unsigned)d >= N_NODES) return;
    float norm = g_dis[s] * ew[e] * g_dis[d];
    const float4* hp = &g_h[(size_t)s * 4];
    float4* ap = &g_agg[(size_t)d * 4];
#pragma unroll
    for (int q = 0; q < 4; q++) {
        float4 v = __ldg(hp + q);
        red_v4(ap + q, make_float4(norm*v.x, norm*v.y, norm*v.z, norm*v.w));
    }
}

// elu(agg + b1) @ W2 -> h2 ; seed out with self-loop dis^2*h2 + b2
__global__ void k_elu_proj2(const float* __restrict__ b1,
                            const float* __restrict__ W2,
                            const float* __restrict__ b2,
                            float* __restrict__ out) {
    __shared__ float sb1[F1], sW2[F1];
    if (threadIdx.x < F1) { sb1[threadIdx.x] = b1[threadIdx.x]; sW2[threadIdx.x] = W2[threadIdx.x]; }
    __syncthreads();

    int i = blockIdx.x * blockDim.x + threadIdx.x;
    if (i >= N_NODES) return;

    float acc = 0.0f;
#pragma unroll
    for (int q = 0; q < 4; q++) {
        float4 v = g_agg[i * 4 + q];
        float vv[4] = {v.x, v.y, v.z, v.w};
#pragma unroll
        for (int j = 0; j < 4; j++) {
            float u = vv[j] + sb1[4*q + j];
            u = (u > 0.0f) ? u : expm1f(u);   // ELU alpha=1
            acc = fmaf(u, sW2[4*q + j], acc);
        }
    }
    g_h2[i] = acc;
    float s = g_dis[i];
    out[i] = s * s * acc + b2[0];
}

// layer-2 edge scatter: out[dst] += norm * h2[src]
__global__ void k_agg2(const int* __restrict__ src,
                       const int* __restrict__ dst,
                       const float* __restrict__ ew,
                       float* __restrict__ out) {
    int e = blockIdx.x * blockDim.x + threadIdx.x;
    if (e >= N_EDGES) return;
    int s = src[e], d = dst[e];
    if ((unsigned)s >= N_NODES || (unsigned)d >= N_NODES) return;
    float norm = g_dis[s] * ew[e] * g_dis[d];
    atomicAdd(&out[d], norm * g_h2[s]);
}

// ---------------- launch ----------------

extern "C" void kernel_launch(void* const* d_in, const int* in_sizes, int n_in,
                              void* d_out, int out_size) {
    const float* x    = (const float*)d_in[0];
    const int*   eidx = (const int*)d_in[1];      // [2, E] int32 (JAX default)
    const float* ew   = (const float*)d_in[2];
    const float* W1   = (const float*)d_in[3];
    const float* b1   = (const float*)d_in[4];
    const float* W2   = (const float*)d_in[5];
    const float* b2   = (const float*)d_in[6];
    float* out = (float*)d_out;

    const int* src = eidx;
    const int* dst = eidx + N_EDGES;

    const int TB = 256;
    int nb_nodes = (N_NODES + TB - 1) / TB;
    int nb_edges = (N_EDGES + TB - 1) / TB;

    k_zero_deg<<<nb_nodes, TB>>>();
    k_deg<<<nb_edges, TB>>>(dst, ew);
    k_dis<<<nb_nodes, TB>>>();
    k_proj1<<<nb_nodes, TB>>>(x, W1);
    k_agg1<<<nb_edges, TB>>>(src, dst, ew);
    k_elu_proj2<<<nb_nodes, TB>>>(b1, W2, b2, out);
    k_agg2<<<nb_edges, TB>>>(src, dst, ew, out);
}

// round 3
// speedup vs baseline: 1.4209x; 1.4209x over previous
#include <cuda_runtime.h>
#include <cuda_fp16.h>
#include <math.h>

#define NN 1000000
#define NE 16000000

// ---- scratch (device globals) ----
__device__ float   g_deg[NN];
__device__ float   g_dis[NN];        // rsqrt(deg+1)
__device__ __half2 g_hs[NN * 8];     // dis[i]*h[i], 16 fp16 features
__device__ float4  g_agg[NN * 4];    // layer-1 accumulation (pre dis[dst] scale)
__device__ float   g_h2s[NN];        // dis[i]*h2[i]

// ---------------- kernels ----------------

__global__ void k_zero() {
    int i = blockIdx.x * blockDim.x + threadIdx.x;
    if (i < NN) g_deg[i] = 0.0f;
}

__global__ void k_deg(const int4* __restrict__ dst4,
                      const float4* __restrict__ ew4) {
    int t = blockIdx.x * blockDim.x + threadIdx.x;
    if (t >= NE / 4) return;
    int4 d = __ldcs(dst4 + t);
    float4 w = __ldcs(ew4 + t);
    if ((unsigned)d.x < NN) atomicAdd(&g_deg[d.x], w.x);
    if ((unsigned)d.y < NN) atomicAdd(&g_deg[d.y], w.y);
    if ((unsigned)d.z < NN) atomicAdd(&g_deg[d.z], w.z);
    if ((unsigned)d.w < NN) atomicAdd(&g_deg[d.w], w.w);
}

__global__ void k_dis() {
    int i = blockIdx.x * blockDim.x + threadIdx.x;
    if (i < NN) g_dis[i] = rsqrtf(g_deg[i] + 1.0f);
}

// h = x @ W1 (smem-staged x tile); store g_hs = dis*h (fp16) and seed g_agg = dis*h (fp32)
__global__ void __launch_bounds__(256) k_proj1(const float* __restrict__ x,
                                               const float* __restrict__ W1) {
    __shared__ float sx[256 * 25];
    __shared__ float sW[25 * 16];
    int i0 = blockIdx.x * 256;
    int nb = min(256, NN - i0);
    int nf4 = (nb * 25) / 4;                      // nb multiple of 4 => exact
    const float4* xg = (const float4*)(x + (size_t)i0 * 25);
    for (int t = threadIdx.x; t < nf4; t += 256) ((float4*)sx)[t] = __ldcs(xg + t);
    for (int t = threadIdx.x; t < 400; t += 256) sW[t] = W1[t];
    __syncthreads();

    int li = threadIdx.x;
    if (li >= nb) return;
    int i = i0 + li;

    float a[16];
#pragma unroll
    for (int f = 0; f < 16; f++) a[f] = 0.0f;
#pragma unroll
    for (int k = 0; k < 25; k++) {
        float xv = sx[li * 25 + k];
#pragma unroll
        for (int f = 0; f < 16; f++) a[f] = fmaf(xv, sW[k * 16 + f], a[f]);
    }

    float s = g_dis[i];
    size_t hb = (size_t)i * 8;
#pragma unroll
    for (int q = 0; q < 4; q++) {
        float4 hv = make_float4(s * a[4*q+0], s * a[4*q+1], s * a[4*q+2], s * a[4*q+3]);
        g_agg[(size_t)i * 4 + q] = hv;                       // self-loop seed (dis*h)
        g_hs[hb + 2*q + 0] = __floats2half2_rn(hv.x, hv.y);
        g_hs[hb + 2*q + 1] = __floats2half2_rn(hv.z, hv.w);
    }
}

__device__ __forceinline__ void red_v4(float4* addr, float4 v) {
    asm volatile("red.global.add.v4.f32 [%0], {%1,%2,%3,%4};"
                 :: "l"(addr), "f"(v.x), "f"(v.y), "f"(v.z), "f"(v.w)
                 : "memory");
}

__device__ __forceinline__ void agg1_one(int s, int d, float w) {
    if ((unsigned)s >= NN || (unsigned)d >= NN) return;
    const uint4* hp = (const uint4*)(g_hs + (size_t)s * 8);
    uint4 p0 = __ldg(hp);
    uint4 p1 = __ldg(hp + 1);
    float4* ap = &g_agg[(size_t)d * 4];
    float2 f0 = __half22float2(*(__half2*)&p0.x);
    float2 f1 = __half22float2(*(__half2*)&p0.y);
    float2 f2 = __half22float2(*(__half2*)&p0.z);
    float2 f3 = __half22float2(*(__half2*)&p0.w);
    red_v4(ap + 0, make_float4(w*f0.x, w*f0.y, w*f1.x, w*f1.y));
    red_v4(ap + 1, make_float4(w*f2.x, w*f2.y, w*f3.x, w*f3.y));
    float2 g0 = __half22float2(*(__half2*)&p1.x);
    float2 g1 = __half22float2(*(__half2*)&p1.y);
    float2 g2 = __half22float2(*(__half2*)&p1.z);
    float2 g3 = __half22float2(*(__half2*)&p1.w);
    red_v4(ap + 2, make_float4(w*g0.x, w*g0.y, w*g1.x, w*g1.y));
    red_v4(ap + 3, make_float4(w*g2.x, w*g2.y, w*g3.x, w*g3.y));
}

// layer-1 edge scatter: agg[dst] += ew * (dis*h)[src]
__global__ void k_agg1(const int4* __restrict__ src4,
                       const int4* __restrict__ dst4,
                       const float4* __restrict__ ew4) {
    int t = blockIdx.x * blockDim.x + threadIdx.x;
    if (t >= NE / 4) return;
    int4 s = __ldcs(src4 + t);
    int4 d = __ldcs(dst4 + t);
    float4 w = __ldcs(ew4 + t);
    agg1_one(s.x, d.x, w.x);
    agg1_one(s.y, d.y, w.y);
    agg1_one(s.z, d.z, w.z);
    agg1_one(s.w, d.w, w.w);
}

// layer1 finish: u = dis[i]*agg + b1 -> ELU -> h2 = u@W2;
// store g_h2s = dis*h2; seed out[i] = g_h2s[i] (pre final dis scale)
__global__ void k_elu_proj2(const float* __restrict__ b1,
                            const float* __restrict__ W2,
                            float* __restrict__ out) {
    __shared__ float sb1[16], sW2[16];
    if (threadIdx.x < 16) { sb1[threadIdx.x] = b1[threadIdx.x]; sW2[threadIdx.x] = W2[threadIdx.x]; }
    __syncthreads();

    int i = blockIdx.x * blockDim.x + threadIdx.x;
    if (i >= NN) return;

    float s = g_dis[i];
    float acc = 0.0f;
#pragma unroll
    for (int q = 0; q < 4; q++) {
        float4 v = g_agg[(size_t)i * 4 + q];
        float vv[4] = {v.x, v.y, v.z, v.w};
#pragma unroll
        for (int j = 0; j < 4; j++) {
            float u = fmaf(s, vv[j], sb1[4*q + j]);
            u = (u > 0.0f) ? u : expm1f(u);       // ELU alpha=1
            acc = fmaf(u, sW2[4*q + j], acc);
        }
    }
    float hs = s * acc;
    g_h2s[i] = hs;
    out[i] = hs;                                   // self-loop seed
}

__device__ __forceinline__ void red_f32(float* addr, float v) {
    asm volatile("red.global.add.f32 [%0], %1;" :: "l"(addr), "f"(v) : "memory");
}

// layer-2 edge scatter: out[dst] += ew * (dis*h2)[src]
__global__ void k_agg2(const int4* __restrict__ src4,
                       const int4* __restrict__ dst4,
                       const float4* __restrict__ ew4,
                       float* __restrict__ out) {
    int t = blockIdx.x * blockDim.x + threadIdx.x;
    if (t >= NE / 4) return;
    int4 s = __ldcs(src4 + t);
    int4 d = __ldcs(dst4 + t);
    float4 w = __ldcs(ew4 + t);
    if ((unsigned)s.x < NN && (unsigned)d.x < NN) red_f32(&out[d.x], w.x * __ldg(&g_h2s[s.x]));
    if ((unsigned)s.y < NN && (unsigned)d.y < NN) red_f32(&out[d.y], w.y * __ldg(&g_h2s[s.y]));
    if ((unsigned)s.z < NN && (unsigned)d.z < NN) red_f32(&out[d.z], w.z * __ldg(&g_h2s[s.z]));
    if ((unsigned)s.w < NN && (unsigned)d.w < NN) red_f32(&out[d.w], w.w * __ldg(&g_h2s[s.w]));
}

// final scale: out = dis*out + b2
__global__ void k_final(float* __restrict__ out, const float* __restrict__ b2) {
    int i = blockIdx.x * blockDim.x + threadIdx.x;
    if (i < NN) out[i] = fmaf(g_dis[i], out[i], b2[0]);
}

// ---------------- launch ----------------

extern "C" void kernel_launch(void* const* d_in, const int* in_sizes, int n_in,
                              void* d_out, int out_size) {
    const float* x    = (const float*)d_in[0];
    const int*   eidx = (const int*)d_in[1];      // [2, E] int32
    const float* ew   = (const float*)d_in[2];
    const float* W1   = (const float*)d_in[3];
    const float* b1   = (const float*)d_in[4];
    const float* W2   = (const float*)d_in[5];
    const float* b2   = (const float*)d_in[6];
    float* out = (float*)d_out;

    const int4*   src4 = (const int4*)eidx;
    const int4*   dst4 = (const int4*)(eidx + NE);
    const float4* ew4  = (const float4*)ew;

    const int TB = 256;
    int nb_nodes = (NN + TB - 1) / TB;
    int nb_e4    = (NE / 4 + TB - 1) / TB;

    k_zero<<<nb_nodes, TB>>>();
    k_deg<<<nb_e4, TB>>>(dst4, ew4);
    k_dis<<<nb_nodes, TB>>>();
    k_proj1<<<nb_nodes, TB>>>(x, W1);
    k_agg1<<<nb_e4, TB>>>(src4, dst4, ew4);
    k_elu_proj2<<<nb_nodes, TB>>>(b1, W2, out);
    k_agg2<<<nb_e4, TB>>>(src4, dst4, ew4, out);
    k_final<<<nb_nodes, TB>>>(out, b2);
}